// round 7
// baseline (speedup 1.0000x reference)
#include <cuda_runtime.h>
#include <cstdint>

// ---------------------------------------------------------------------------
// SetAbstraction (PointNet++): FPS -> ball query -> MLP -> max
// B=2, N=16384, S=4096, K=32, F_IN=16, hidden 64-64-128
// Round 7 FPS: R4 skeleton (warp-wide cell scans, lane-owned cells) with
//   - per-cell packed u64 keys via shared-memory atomicMax (no per-cell
//     collective argmax, no identity broadcasts)
//   - bank-safe key storage (lane-contiguous; fixes R6's 32-way conflict)
//   - winner located by rescanning only the winning cell (L1-hot)
//   - per-lane self-prefetch of touched cells
// Selection sequence bit-identical to the naive scan.
// ---------------------------------------------------------------------------

#define BB   2
#define NN   16384
#define SS   4096
#define KK   32
#define FIN  16
#define HOUT 128
#define GC    8
#define NCELL 512
#define CW    0.125f
#define FULLM 0xffffffffu

// ---- scratch (__device__ globals; no allocation allowed) -------------------
__device__ float g_centers[BB * SS * 3];
__device__ int   g_nbr[BB * SS * KK];
__device__ int   g_cnt[BB * SS];

__device__ float2 g_sxy[BB * NN];      // sorted (x,y)
__device__ int2   g_szi[BB * NN];      // sorted (z bits, orig idx)
__device__ int    g_hist[BB * NCELL];
__device__ int    g_cstart[BB * (NCELL + 1)];
__device__ int    g_fill[BB * NCELL];

__device__ __forceinline__ int cell_of(float x, float y, float z) {
    int ix = (int)(x * (float)GC); ix = ix < 0 ? 0 : (ix > GC - 1 ? GC - 1 : ix);
    int iy = (int)(y * (float)GC); iy = iy < 0 ? 0 : (iy > GC - 1 ? GC - 1 : iy);
    int iz = (int)(z * (float)GC); iz = iz < 0 ? 0 : (iz > GC - 1 ? GC - 1 : iz);
    return (iz * GC + iy) * GC + ix;
}

// ===========================================================================
// Preprocessing: histogram -> scan -> scatter (counting sort by cell)
// ===========================================================================
__global__ void init_hist_kernel() {
    int i = blockIdx.x * blockDim.x + threadIdx.x;
    if (i < BB * NCELL) g_hist[i] = 0;
}

__global__ void cell_count_kernel(const float* __restrict__ pos) {
    int i = blockIdx.x * blockDim.x + threadIdx.x;
    if (i >= BB * NN) return;
    int b = i >> 14;
    float x = pos[(size_t)i * 3 + 0], y = pos[(size_t)i * 3 + 1], z = pos[(size_t)i * 3 + 2];
    atomicAdd(&g_hist[b * NCELL + cell_of(x, y, z)], 1);
}

__global__ void cell_scan_kernel() {
    __shared__ int sh[NCELL];
    __shared__ int ss[NCELL + 1];
    int b = blockIdx.x, tid = threadIdx.x;
    if (tid < NCELL) sh[tid] = g_hist[b * NCELL + tid];
    __syncthreads();
    if (tid == 0) {
        int acc = 0;
        for (int c = 0; c < NCELL; c++) { ss[c] = acc; acc += sh[c]; }
        ss[NCELL] = acc;
    }
    __syncthreads();
    if (tid < NCELL) {
        g_cstart[b * (NCELL + 1) + tid] = ss[tid];
        g_fill[b * NCELL + tid] = ss[tid];
    }
    if (tid == 0) g_cstart[b * (NCELL + 1) + NCELL] = ss[NCELL];
}

__global__ void cell_scatter_kernel(const float* __restrict__ pos) {
    int i = blockIdx.x * blockDim.x + threadIdx.x;
    if (i >= BB * NN) return;
    int b = i >> 14;
    int li = i & (NN - 1);
    float x = pos[(size_t)i * 3 + 0], y = pos[(size_t)i * 3 + 1], z = pos[(size_t)i * 3 + 2];
    int c = cell_of(x, y, z);
    int p = atomicAdd(&g_fill[b * NCELL + c], 1);
    g_sxy[b * NN + p] = make_float2(x, y);
    g_szi[b * NN + p] = make_int2(__float_as_int(z), li);
}

// ===========================================================================
// Kernel 1: grid-pruned exact FPS. One block per batch, 512 threads (16 warps).
// Warp w owns cells {w + 16*l}; cell key stored at s_key[w*32 + l] (bank-safe).
// Key = (dmin_bits << 32) | ~orig_idx : atomicMax gives (max dmin, min idx).
// ===========================================================================
__global__ void __launch_bounds__(512, 1)
fps_kernel(const float* __restrict__ pos, float* __restrict__ out_centers)
{
    extern __shared__ float sm[];
    float2* s_xy   = (float2*)sm;        // NN float2 (128 KB)
    float*  s_dmin = sm + 2 * NN;        // NN floats (64 KB)

    __shared__ unsigned long long s_key[NCELL];    // storage idx = w*32 + l
    __shared__ unsigned long long s_part[16];      // cached per-warp partial
    __shared__ int                s_pcell[16];     // partial winner cell (geometric)
    __shared__ int                s_cs[NCELL + 1];
    __shared__ float              s_c[3];

    const int b = blockIdx.x, tid = threadIdx.x;
    const int w = tid >> 5, lane = tid & 31;
    const int base = b * NN;
    const int sidx = (w << 5) + lane;              // my cell's key slot
    const int cell = w + (lane << 4);              // my geometric cell

    for (int p = tid; p < NN; p += 512) {
        s_xy[p] = g_sxy[base + p];
        s_dmin[p] = 1e10f;
    }
    for (int c = tid; c <= NCELL; c += 512) s_cs[c] = g_cstart[b * (NCELL + 1) + c];
    s_key[sidx] = ((unsigned long long)__float_as_uint(1e10f)) << 32;
    if (tid < 16) { s_part[tid] = 0ULL; s_pcell[tid] = 0; }

    const int cs0 = g_cstart[b * (NCELL + 1) + cell];
    const int cs1 = g_cstart[b * (NCELL + 1) + cell + 1];
    const int ix = cell & 7, iy = (cell >> 3) & 7, iz = cell >> 6;
    const float bcx = ((float)ix + 0.5f) * CW;
    const float bcy = ((float)iy + 0.5f) * CW;
    const float bcz = ((float)iz + 0.5f) * CW;
    const float hw  = 0.5f * CW + 1e-5f;

    if (tid == 0) {
        float cx = pos[(size_t)base * 3 + 0];
        float cy = pos[(size_t)base * 3 + 1];
        float cz = pos[(size_t)base * 3 + 2];
        s_c[0] = cx; s_c[1] = cy; s_c[2] = cz;
        int row = b * SS;
        out_centers[row * 3 + 0] = cx; out_centers[row * 3 + 1] = cy; out_centers[row * 3 + 2] = cz;
        g_centers[row * 3 + 0]   = cx; g_centers[row * 3 + 1]   = cy; g_centers[row * 3 + 2]   = cz;
    }
    __syncthreads();

    for (int t = 1; t < SS; t++) {
        const float ccx = s_c[0], ccy = s_c[1], ccz = s_c[2];

        // --- prune: each lane checks its own cell vs cached key -----------
        float pdx = fmaxf(fabsf(ccx - bcx) - hw, 0.f);
        float pdy = fmaxf(fabsf(ccy - bcy) - hw, 0.f);
        float pdz = fmaxf(fabsf(ccz - bcz) - hw, 0.f);
        float lb  = (pdx * pdx + pdy * pdy + pdz * pdz) * 0.999f;
        unsigned mykv = (unsigned)(s_key[sidx] >> 32);
        bool touched = lb < __uint_as_float(mykv);
        unsigned tmask = __ballot_sync(FULLM, touched);

        if (tmask) {
            if (touched) {
                s_key[sidx] = 0ULL;                       // reset before rescan
                const int2* a0 = &g_szi[base + cs0];      // self-prefetch (2 lines)
                asm volatile("prefetch.global.L1 [%0];" :: "l"(a0));
                if (cs0 + 16 < cs1) {
                    const int2* a1 = &g_szi[base + cs0 + 16];
                    asm volatile("prefetch.global.L1 [%0];" :: "l"(a1));
                }
            }
            __syncwarp();

            // process touched cells (warp-wide scan per cell)
            unsigned pm = tmask;
            while (pm) {
                int j = __ffs(pm) - 1; pm &= pm - 1;
                int st = __shfl_sync(FULLM, cs0, j);
                int en = __shfl_sync(FULLM, cs1, j);
                unsigned long long best = 0ULL;
                for (int p0 = st; p0 < en; p0 += 32) {
                    int p = p0 + lane;
                    if (p < en) {
                        int2   zi = g_szi[base + p];
                        float2 xy = s_xy[p];
                        float zz  = __int_as_float(zi.x);
                        float ddx = __fsub_rn(xy.x, ccx);
                        float ddy = __fsub_rn(xy.y, ccy);
                        float ddz = __fsub_rn(zz,   ccz);
                        float d   = __fadd_rn(__fadd_rn(__fmul_rn(ddx, ddx), __fmul_rn(ddy, ddy)),
                                              __fmul_rn(ddz, ddz));
                        float dm  = fminf(s_dmin[p], d);
                        s_dmin[p] = dm;
                        unsigned long long pk =
                            (((unsigned long long)__float_as_uint(dm)) << 32) |
                            (unsigned long long)(~(unsigned)zi.y);
                        if (pk > best) best = pk;
                    }
                }
                if (best) atomicMax(&s_key[(w << 5) + j], best);
            }
            __syncwarp();

            // per-warp partial over its 32 owned cells (bank-safe LDS.64)
            unsigned long long k2 = s_key[sidx];
            unsigned hi = (unsigned)(k2 >> 32), lo2 = (unsigned)k2;
            unsigned mv   = __reduce_max_sync(FULLM, hi);
            unsigned cand = (hi == mv) ? lo2 : 0u;
            unsigned mlo  = __reduce_max_sync(FULLM, cand);
            unsigned bm   = __ballot_sync(FULLM, (hi == mv) && (lo2 == mlo));
            if (lane == __ffs(bm) - 1) { s_part[w] = k2; s_pcell[w] = cell; }
        }
        __syncthreads();   // scans + partials visible

        // --- warp 0: final argmax over 16 cached partials + locate winner --
        if (w == 0) {
            unsigned long long pk = (lane < 16) ? s_part[lane] : 0ULL;
            int pc = (lane < 16) ? s_pcell[lane] : 0;
            unsigned hi = (unsigned)(pk >> 32), lo2 = (unsigned)pk;
            unsigned mv   = __reduce_max_sync(FULLM, hi);
            unsigned cand = (hi == mv) ? lo2 : 0u;
            unsigned mlo  = __reduce_max_sync(FULLM, cand);
            unsigned bm   = __ballot_sync(FULLM, (hi == mv) && (cand == mlo));
            int src = __ffs(bm) - 1;
            int wc  = __shfl_sync(FULLM, pc, src);
            int oi  = (int)(~mlo);

            // locate winner point inside cell wc (matches unique orig idx)
            int st = s_cs[wc], en = s_cs[wc + 1];
            for (int p0 = st; p0 < en; p0 += 32) {
                int p = p0 + lane;
                bool hitp = false;
                if (p < en) {
                    hitp = (__float_as_uint(s_dmin[p]) == mv) && (g_szi[base + p].y == oi);
                }
                unsigned mm = __ballot_sync(FULLM, hitp);
                if (mm) {
                    if (hitp && lane == __ffs(mm) - 1) {
                        float2 xyw = s_xy[p];
                        float  zw  = __int_as_float(g_szi[base + p].x);
                        s_c[0] = xyw.x; s_c[1] = xyw.y; s_c[2] = zw;
                        int row = b * SS + t;
                        out_centers[row * 3 + 0] = xyw.x; out_centers[row * 3 + 1] = xyw.y; out_centers[row * 3 + 2] = zw;
                        g_centers[row * 3 + 0]   = xyw.x; g_centers[row * 3 + 1]   = xyw.y; g_centers[row * 3 + 2]   = zw;
                    }
                    break;
                }
            }
        }
        __syncthreads();   // s_c visible; protect key reads vs next-iter writes
    }
}

// ===========================================================================
// Kernel 2: Ball query — one warp per center; ordered scan, first K within R.
// ===========================================================================
__global__ void __launch_bounds__(256, 8)
ballq_kernel(const float* __restrict__ pos, float* __restrict__ out_batch)
{
    const int w    = (blockIdx.x * blockDim.x + threadIdx.x) >> 5;
    const int lane = threadIdx.x & 31;
    if (w >= BB * SS) return;

    const int b = w >> 12;
    const int s = w & (SS - 1);
    const float* pb = pos + (size_t)b * NN * 3;

    const float cx = g_centers[w * 3 + 0];
    const float cy = g_centers[w * 3 + 1];
    const float cz = g_centers[w * 3 + 2];
    const float R2 = (float)(0.1 * 0.1);
    const int excl = s - b * (NN - SS);

    int cnt = 0;
    for (int j0 = 0; j0 < NN && cnt < KK; j0 += 32) {
        int j = j0 + lane;
        float x_ = pb[j * 3 + 0];
        float y_ = pb[j * 3 + 1];
        float z_ = pb[j * 3 + 2];
        float dx = __fsub_rn(cx, x_);
        float dy = __fsub_rn(cy, y_);
        float dz = __fsub_rn(cz, z_);
        float d2 = __fadd_rn(__fadd_rn(__fmul_rn(dx, dx), __fmul_rn(dy, dy)),
                             __fmul_rn(dz, dz));
        bool hit = (d2 <= R2) && (j != excl);
        unsigned m = __ballot_sync(0xffffffffu, hit);
        while (m && cnt < KK) {
            int bit = __ffs(m) - 1;
            if (lane == bit) g_nbr[w * KK + cnt] = j0 + bit;
            cnt++;
            m &= m - 1;
        }
    }
    if (lane == 0) {
        g_cnt[w] = cnt;
        out_batch[w] = (float)b;
    }
}

// ===========================================================================
// Kernel 3: gather + MLP(19->64->64->128) + max over K+1 (unchanged).
// ===========================================================================
__global__ void __launch_bounds__(256, 1)
mlp_kernel(const float* __restrict__ x, const float* __restrict__ pos,
           const float* __restrict__ W1, const float* __restrict__ B1,
           const float* __restrict__ W2, const float* __restrict__ B2,
           const float* __restrict__ W3, const float* __restrict__ B3,
           float* __restrict__ out_x)
{
    extern __shared__ float sw[];
    float* sW1 = sw;
    float* sb1 = sW1 + 19 * 64;
    float* sW2 = sb1 + 64;
    float* sb2 = sW2 + 4096;
    float* sW3 = sb2 + 64;
    float* sb3 = sW3 + 8192;

    const int tid = threadIdx.x;
    for (int i = tid; i < 19 * 64; i += 256) sW1[i] = W1[i];
    for (int i = tid; i < 64;      i += 256) sb1[i] = B1[i];
    for (int i = tid; i < 64 * 64; i += 256) sW2[i] = W2[i];
    for (int i = tid; i < 64;      i += 256) sb2[i] = B2[i];
    for (int i = tid; i < 64 * 128; i += 256) sW3[i] = W3[i];
    for (int i = tid; i < 128;     i += 256) sb3[i] = B3[i];
    __syncthreads();

    const int lane = tid & 31;
    const int c    = blockIdx.x * 8 + (tid >> 5);
    const int b    = c >> 12;
    const int s    = c & (SS - 1);

    const float cx = g_centers[c * 3 + 0];
    const float cy = g_centers[c * 3 + 1];
    const float cz = g_centers[c * 3 + 2];
    const float ccomp = (lane == 16) ? cx : ((lane == 17) ? cy : cz);
    const int cnt = g_cnt[c];

    float m0 = -3.0e38f, m1 = -3.0e38f, m2 = -3.0e38f, m3 = -3.0e38f;

    auto process4 = [&](const int rows[4], int nv) {
        float fv[4];
#pragma unroll
        for (int e = 0; e < 4; e++) {
            int r = rows[e];
            float v = 0.f;
            if (lane < FIN)          v = x[(size_t)r * FIN + lane];
            else if (lane < FIN + 3) v = pos[(size_t)r * 3 + (lane - FIN)] - ccomp;
            fv[e] = (e < nv) ? v : 0.f;
        }
        float a0[4], a1[4];
#pragma unroll
        for (int e = 0; e < 4; e++) { a0[e] = sb1[lane]; a1[e] = sb1[lane + 32]; }
#pragma unroll
        for (int i = 0; i < FIN + 3; i++) {
            float w0 = sW1[i * 64 + lane];
            float w1 = sW1[i * 64 + 32 + lane];
#pragma unroll
            for (int e = 0; e < 4; e++) {
                float v = __shfl_sync(0xffffffffu, fv[e], i);
                a0[e] = fmaf(v, w0, a0[e]);
                a1[e] = fmaf(v, w1, a1[e]);
            }
        }
#pragma unroll
        for (int e = 0; e < 4; e++) { a0[e] = fmaxf(a0[e], 0.f); a1[e] = fmaxf(a1[e], 0.f); }

        float g0[4], g1[4];
#pragma unroll
        for (int e = 0; e < 4; e++) { g0[e] = sb2[lane]; g1[e] = sb2[lane + 32]; }
#pragma unroll
        for (int i = 0; i < 64; i++) {
            float w0 = sW2[i * 64 + lane];
            float w1 = sW2[i * 64 + 32 + lane];
#pragma unroll
            for (int e = 0; e < 4; e++) {
                float v = (i < 32) ? __shfl_sync(0xffffffffu, a0[e], i)
                                   : __shfl_sync(0xffffffffu, a1[e], i - 32);
                g0[e] = fmaf(v, w0, g0[e]);
                g1[e] = fmaf(v, w1, g1[e]);
            }
        }
#pragma unroll
        for (int e = 0; e < 4; e++) { g0[e] = fmaxf(g0[e], 0.f); g1[e] = fmaxf(g1[e], 0.f); }

        float h0[4], h1v[4], h2v[4], h3v[4];
#pragma unroll
        for (int e = 0; e < 4; e++) {
            h0[e]  = sb3[lane];       h1v[e] = sb3[lane + 32];
            h2v[e] = sb3[lane + 64];  h3v[e] = sb3[lane + 96];
        }
#pragma unroll
        for (int i = 0; i < 64; i++) {
            float w0 = sW3[i * 128 + lane];
            float w1 = sW3[i * 128 + 32 + lane];
            float w2 = sW3[i * 128 + 64 + lane];
            float w3 = sW3[i * 128 + 96 + lane];
#pragma unroll
            for (int e = 0; e < 4; e++) {
                float v = (i < 32) ? __shfl_sync(0xffffffffu, g0[e], i)
                                   : __shfl_sync(0xffffffffu, g1[e], i - 32);
                h0[e]  = fmaf(v, w0, h0[e]);
                h1v[e] = fmaf(v, w1, h1v[e]);
                h2v[e] = fmaf(v, w2, h2v[e]);
                h3v[e] = fmaf(v, w3, h3v[e]);
            }
        }
#pragma unroll
        for (int e = 0; e < 4; e++) {
            if (e < nv) {
                m0 = fmaxf(m0, h0[e]);  m1 = fmaxf(m1, h1v[e]);
                m2 = fmaxf(m2, h2v[e]); m3 = fmaxf(m3, h3v[e]);
            }
        }
    };

    for (int eb = 0; eb < cnt; eb += 4) {
        int nv = min(4, cnt - eb);
        int rows[4];
#pragma unroll
        for (int e = 0; e < 4; e++) {
            int kk = eb + ((e < nv) ? e : 0);
            rows[e] = b * NN + g_nbr[c * KK + kk];
        }
        process4(rows, nv);
    }
    {
        int dflat = b * SS + s;
        int rows[4] = { dflat, dflat, dflat, dflat };
        process4(rows, 1);
    }

    out_x[(size_t)c * HOUT + lane]      = m0;
    out_x[(size_t)c * HOUT + lane + 32] = m1;
    out_x[(size_t)c * HOUT + lane + 64] = m2;
    out_x[(size_t)c * HOUT + lane + 96] = m3;
}

// ===========================================================================
// launch
// ===========================================================================
extern "C" void kernel_launch(void* const* d_in, const int* in_sizes, int n_in,
                              void* d_out, int out_size)
{
    const float* x   = (const float*)d_in[0];
    const float* pos = (const float*)d_in[1];
    const float* W1 = (const float*)d_in[3];
    const float* B1 = (const float*)d_in[4];
    const float* W2 = (const float*)d_in[5];
    const float* B2 = (const float*)d_in[6];
    const float* W3 = (const float*)d_in[7];
    const float* B3 = (const float*)d_in[8];

    float* out_x = (float*)d_out;
    float* out_c = out_x + (size_t)BB * SS * HOUT;
    float* out_b = out_c + (size_t)BB * SS * 3;

    const size_t fps_smem = (size_t)3 * NN * sizeof(float);   // 192 KB dynamic
    const size_t mlp_smem = (size_t)13760 * sizeof(float);
    cudaFuncSetAttribute(fps_kernel, cudaFuncAttributeMaxDynamicSharedMemorySize, (int)fps_smem);
    cudaFuncSetAttribute(mlp_kernel, cudaFuncAttributeMaxDynamicSharedMemorySize, (int)mlp_smem);

    init_hist_kernel<<<(BB * NCELL + 255) / 256, 256>>>();
    cell_count_kernel<<<(BB * NN + 255) / 256, 256>>>(pos);
    cell_scan_kernel<<<BB, NCELL>>>();
    cell_scatter_kernel<<<(BB * NN + 255) / 256, 256>>>(pos);
    fps_kernel<<<BB, 512, fps_smem>>>(pos, out_c);
    ballq_kernel<<<(BB * SS * 32) / 256, 256>>>(pos, out_b);
    mlp_kernel<<<(BB * SS) / 8, 256, mlp_smem>>>(x, pos, W1, B1, W2, B2, W3, B3, out_x);
}

// round 8
// speedup vs baseline: 1.7137x; 1.7137x over previous
#include <cuda_runtime.h>
#include <cstdint>

// ---------------------------------------------------------------------------
// SetAbstraction (PointNet++): FPS -> ball query -> MLP -> max
// B=2, N=16384, S=4096, K=32, F_IN=16, hidden 64-64-128
// Round 8 FPS: R4 skeleton (warp-wide cell scans, lane-owned cells, pipelined
// next-cell preload) with packed-identity REDUX reduction:
//   per-lane key u64 = (dmin_bits<<28) | (~origidx&0x3fff)<<14 | sorted_pos.
//   Two __reduce_max_sync's yield (max dmin, min origidx) AND the winner's
//   position -- no ballot/ffs, no identity-broadcast shuffles, no atomics.
// Selection sequence bit-identical to the naive scan.
// ---------------------------------------------------------------------------

#define BB   2
#define NN   16384
#define SS   4096
#define KK   32
#define FIN  16
#define HOUT 128
#define GC    8
#define NCELL 512
#define CW    0.125f
#define FULLM 0xffffffffu

// ---- scratch (__device__ globals; no allocation allowed) -------------------
__device__ float g_centers[BB * SS * 3];
__device__ int   g_nbr[BB * SS * KK];
__device__ int   g_cnt[BB * SS];

__device__ float2 g_sxy[BB * NN];      // sorted (x,y)
__device__ int2   g_szi[BB * NN];      // sorted (z bits, orig idx)
__device__ int    g_hist[BB * NCELL];
__device__ int    g_cstart[BB * (NCELL + 1)];
__device__ int    g_fill[BB * NCELL];

__device__ __forceinline__ int cell_of(float x, float y, float z) {
    int ix = (int)(x * (float)GC); ix = ix < 0 ? 0 : (ix > GC - 1 ? GC - 1 : ix);
    int iy = (int)(y * (float)GC); iy = iy < 0 ? 0 : (iy > GC - 1 ? GC - 1 : iy);
    int iz = (int)(z * (float)GC); iz = iz < 0 ? 0 : (iz > GC - 1 ? GC - 1 : iz);
    return (iz * GC + iy) * GC + ix;
}

// ===========================================================================
// Preprocessing: histogram -> scan -> scatter (counting sort by cell)
// ===========================================================================
__global__ void init_hist_kernel() {
    int i = blockIdx.x * blockDim.x + threadIdx.x;
    if (i < BB * NCELL) g_hist[i] = 0;
}

__global__ void cell_count_kernel(const float* __restrict__ pos) {
    int i = blockIdx.x * blockDim.x + threadIdx.x;
    if (i >= BB * NN) return;
    int b = i >> 14;
    float x = pos[(size_t)i * 3 + 0], y = pos[(size_t)i * 3 + 1], z = pos[(size_t)i * 3 + 2];
    atomicAdd(&g_hist[b * NCELL + cell_of(x, y, z)], 1);
}

__global__ void cell_scan_kernel() {
    __shared__ int sh[NCELL];
    __shared__ int ss[NCELL + 1];
    int b = blockIdx.x, tid = threadIdx.x;
    if (tid < NCELL) sh[tid] = g_hist[b * NCELL + tid];
    __syncthreads();
    if (tid == 0) {
        int acc = 0;
        for (int c = 0; c < NCELL; c++) { ss[c] = acc; acc += sh[c]; }
        ss[NCELL] = acc;
    }
    __syncthreads();
    if (tid < NCELL) {
        g_cstart[b * (NCELL + 1) + tid] = ss[tid];
        g_fill[b * NCELL + tid] = ss[tid];
    }
    if (tid == 0) g_cstart[b * (NCELL + 1) + NCELL] = ss[NCELL];
}

__global__ void cell_scatter_kernel(const float* __restrict__ pos) {
    int i = blockIdx.x * blockDim.x + threadIdx.x;
    if (i >= BB * NN) return;
    int b = i >> 14;
    int li = i & (NN - 1);
    float x = pos[(size_t)i * 3 + 0], y = pos[(size_t)i * 3 + 1], z = pos[(size_t)i * 3 + 2];
    int c = cell_of(x, y, z);
    int p = atomicAdd(&g_fill[b * NCELL + c], 1);
    g_sxy[b * NN + p] = make_float2(x, y);
    g_szi[b * NN + p] = make_int2(__float_as_int(z), li);
}

// ===========================================================================
// Kernel 1: grid-pruned exact FPS. One block per batch, 512 threads (16 warps).
// Warp w owns cells {w + 16*l}; lane l caches cell key (kv, kcand, kz) in regs.
// ===========================================================================
__global__ void __launch_bounds__(512, 1)
fps_kernel(const float* __restrict__ pos, float* __restrict__ out_centers)
{
    extern __shared__ float sm[];
    float2* s_xy   = (float2*)sm;        // NN float2 (128 KB)
    float*  s_dmin = sm + 2 * NN;        // NN floats (64 KB)

    __shared__ unsigned long long s_part[16];  // per-warp partial: (mv<<32)|mcand
    __shared__ float              s_pz[16];    // per-warp partial winner z
    __shared__ float              s_c[3];

    const int b = blockIdx.x, tid = threadIdx.x;
    const int w = tid >> 5, lane = tid & 31;
    const int base = b * NN;

    for (int p = tid; p < NN; p += 512) {
        s_xy[p] = g_sxy[base + p];
        s_dmin[p] = 1e10f;
    }
    if (tid < 16) { s_part[tid] = 0ULL; s_pz[tid] = 0.f; }

    // this lane's owned cell
    const int cell = w + (lane << 4);
    const int cs0 = g_cstart[b * (NCELL + 1) + cell];
    const int cs1 = g_cstart[b * (NCELL + 1) + cell + 1];
    const int ix = cell & 7, iy = (cell >> 3) & 7, iz = cell >> 6;
    const float lox = (float)ix * CW - 1e-5f, hix = (float)ix * CW + CW + 1e-5f;
    const float loy = (float)iy * CW - 1e-5f, hiy = (float)iy * CW + CW + 1e-5f;
    const float loz = (float)iz * CW - 1e-5f, hiz = (float)iz * CW + CW + 1e-5f;

    unsigned kv    = __float_as_uint(1e10f);   // cached cell key: max dmin bits
    unsigned kcand = 0u;                       // (lo14<<14)|p of winner
    float    kz    = 0.f;                      // winner z

    if (tid == 0) {
        float cx = pos[(size_t)base * 3 + 0];
        float cy = pos[(size_t)base * 3 + 1];
        float cz = pos[(size_t)base * 3 + 2];
        s_c[0] = cx; s_c[1] = cy; s_c[2] = cz;
        int row = b * SS;
        out_centers[row * 3 + 0] = cx; out_centers[row * 3 + 1] = cy; out_centers[row * 3 + 2] = cz;
        g_centers[row * 3 + 0]   = cx; g_centers[row * 3 + 1]   = cy; g_centers[row * 3 + 2]   = cz;
    }
    __syncthreads();

    for (int t = 1; t < SS; t++) {
        const float cx = s_c[0], cy = s_c[1], cz = s_c[2];

        // --- prune: each lane checks its own cell (R4-exact formula) -------
        float pdx = fmaxf(fmaxf(lox - cx, cx - hix), 0.f);
        float pdy = fmaxf(fmaxf(loy - cy, cy - hiy), 0.f);
        float pdz = fmaxf(fmaxf(loz - cz, cz - hiz), 0.f);
        float lb  = (pdx * pdx + pdy * pdy + pdz * pdz) * 0.999f;
        bool touched = lb < __uint_as_float(kv);
        unsigned tmask = __ballot_sync(FULLM, touched);
        const bool any = (tmask != 0);

        // --- process touched cells (pipelined next-cell preload) -----------
        int j = -1, st = 0, en = 0; bool v = false;
        int2 zi = make_int2(0, 0); float2 xy = make_float2(0.f, 0.f);
        if (tmask) {
            j = __ffs(tmask) - 1; tmask &= tmask - 1;
            st = __shfl_sync(FULLM, cs0, j);
            en = __shfl_sync(FULLM, cs1, j);
            int p = st + lane; v = p < en;
            if (v) { zi = g_szi[base + p]; xy = s_xy[p]; }
            if (st + 32 + lane < en) {
                const int2* pf = &g_szi[base + st + 32 + lane];
                asm volatile("prefetch.global.L1 [%0];" :: "l"(pf));
            }
        }
        while (j >= 0) {
            unsigned long long best = 0ULL; float bz = 0.f;
            // chunk 0 (preloaded)
            if (v) {
                int p = st + lane;
                float zz  = __int_as_float(zi.x);
                float ddx = __fsub_rn(xy.x, cx);
                float ddy = __fsub_rn(xy.y, cy);
                float ddz = __fsub_rn(zz,   cz);
                float d   = __fadd_rn(__fadd_rn(__fmul_rn(ddx, ddx), __fmul_rn(ddy, ddy)),
                                      __fmul_rn(ddz, ddz));
                float dm  = fminf(s_dmin[p], d);
                s_dmin[p] = dm;
                unsigned lo14 = (~(unsigned)zi.y) & 0x3fffu;
                best = (((unsigned long long)__float_as_uint(dm)) << 28)
                     | ((unsigned long long)lo14 << 14)
                     | (unsigned long long)p;
                bz = zz;
            }
            // prefetch next touched cell's first chunk(s)
            int jn = -1, stn = 0, enn = 0; bool vn = false;
            int2 zin = make_int2(0, 0); float2 xyn = make_float2(0.f, 0.f);
            if (tmask) {
                jn = __ffs(tmask) - 1; tmask &= tmask - 1;
                stn = __shfl_sync(FULLM, cs0, jn);
                enn = __shfl_sync(FULLM, cs1, jn);
                int p = stn + lane; vn = p < enn;
                if (vn) { zin = g_szi[base + p]; xyn = s_xy[p]; }
                if (stn + 32 + lane < enn) {
                    const int2* pf = &g_szi[base + stn + 32 + lane];
                    asm volatile("prefetch.global.L1 [%0];" :: "l"(pf));
                }
            }
            // remaining chunks of current cell
            for (int p0 = st + 32; p0 < en; p0 += 32) {
                int p = p0 + lane;
                if (p < en) {
                    int2   z2 = g_szi[base + p];
                    float2 x2 = s_xy[p];
                    float zz  = __int_as_float(z2.x);
                    float ddx = __fsub_rn(x2.x, cx);
                    float ddy = __fsub_rn(x2.y, cy);
                    float ddz = __fsub_rn(zz,   cz);
                    float d   = __fadd_rn(__fadd_rn(__fmul_rn(ddx, ddx), __fmul_rn(ddy, ddy)),
                                          __fmul_rn(ddz, ddz));
                    float dm  = fminf(s_dmin[p], d);
                    s_dmin[p] = dm;
                    unsigned lo14 = (~(unsigned)z2.y) & 0x3fffu;
                    unsigned long long pk =
                        (((unsigned long long)__float_as_uint(dm)) << 28)
                        | ((unsigned long long)lo14 << 14)
                        | (unsigned long long)p;
                    if (pk > best) { best = pk; bz = zz; }
                }
            }
            // cell key via packed REDUX (identity rides in the value)
            unsigned du    = (unsigned)(best >> 28);
            unsigned wm    = __reduce_max_sync(FULLM, du);
            unsigned cand  = (du == wm) ? (unsigned)(best & 0xFFFFFFFull) : 0u;
            unsigned mcand = __reduce_max_sync(FULLM, cand);
            int wp  = (int)(mcand & 0x3fffu);
            int src = (wp - st) & 31;
            float zw = __shfl_sync(FULLM, bz, src);
            if (lane == j) { kv = wm; kcand = mcand; kz = zw; }
            j = jn; st = stn; en = enn; v = vn; zi = zin; xy = xyn;
        }

        // --- per-warp partial over its 32 owned cells (skip if untouched) --
        if (any) {
            unsigned mv  = __reduce_max_sync(FULLM, kv);
            unsigned c2  = (kv == mv) ? kcand : 0u;
            unsigned mc2 = __reduce_max_sync(FULLM, c2);
            if (kv == mv && kcand == mc2) {   // unique (mc2 embeds unique p)
                s_part[w] = (((unsigned long long)mv) << 32) | mc2;
                s_pz[w]   = kz;
            }
        }
        __syncthreads();

        // --- warp 0: final argmax over 16 partials, publish center ---------
        if (w == 0) {
            unsigned long long pk = (lane < 16) ? s_part[lane] : 0ULL;
            float pz = (lane < 16) ? s_pz[lane] : 0.f;
            unsigned hi = (unsigned)(pk >> 32), lo = (unsigned)pk;
            unsigned mv2 = __reduce_max_sync(FULLM, hi);
            unsigned c3  = (hi == mv2) ? lo : 0u;
            unsigned mc3 = __reduce_max_sync(FULLM, c3);
            if (hi == mv2 && lo == mc3) {     // unique winner lane
                int wp = (int)(mc3 & 0x3fffu);
                float2 xyw = s_xy[wp];
                s_c[0] = xyw.x; s_c[1] = xyw.y; s_c[2] = pz;
                int row = b * SS + t;
                out_centers[row * 3 + 0] = xyw.x; out_centers[row * 3 + 1] = xyw.y; out_centers[row * 3 + 2] = pz;
                g_centers[row * 3 + 0]   = xyw.x; g_centers[row * 3 + 1]   = xyw.y; g_centers[row * 3 + 2]   = pz;
            }
        }
        __syncthreads();
    }
}

// ===========================================================================
// Kernel 2: Ball query — one warp per center; ordered scan, first K within R.
// ===========================================================================
__global__ void __launch_bounds__(256, 8)
ballq_kernel(const float* __restrict__ pos, float* __restrict__ out_batch)
{
    const int w    = (blockIdx.x * blockDim.x + threadIdx.x) >> 5;
    const int lane = threadIdx.x & 31;
    if (w >= BB * SS) return;

    const int b = w >> 12;
    const int s = w & (SS - 1);
    const float* pb = pos + (size_t)b * NN * 3;

    const float cx = g_centers[w * 3 + 0];
    const float cy = g_centers[w * 3 + 1];
    const float cz = g_centers[w * 3 + 2];
    const float R2 = (float)(0.1 * 0.1);
    const int excl = s - b * (NN - SS);

    int cnt = 0;
    for (int j0 = 0; j0 < NN && cnt < KK; j0 += 32) {
        int j = j0 + lane;
        float x_ = pb[j * 3 + 0];
        float y_ = pb[j * 3 + 1];
        float z_ = pb[j * 3 + 2];
        float dx = __fsub_rn(cx, x_);
        float dy = __fsub_rn(cy, y_);
        float dz = __fsub_rn(cz, z_);
        float d2 = __fadd_rn(__fadd_rn(__fmul_rn(dx, dx), __fmul_rn(dy, dy)),
                             __fmul_rn(dz, dz));
        bool hit = (d2 <= R2) && (j != excl);
        unsigned m = __ballot_sync(0xffffffffu, hit);
        while (m && cnt < KK) {
            int bit = __ffs(m) - 1;
            if (lane == bit) g_nbr[w * KK + cnt] = j0 + bit;
            cnt++;
            m &= m - 1;
        }
    }
    if (lane == 0) {
        g_cnt[w] = cnt;
        out_batch[w] = (float)b;
    }
}

// ===========================================================================
// Kernel 3: gather + MLP(19->64->64->128) + max over K+1 (unchanged).
// ===========================================================================
__global__ void __launch_bounds__(256, 1)
mlp_kernel(const float* __restrict__ x, const float* __restrict__ pos,
           const float* __restrict__ W1, const float* __restrict__ B1,
           const float* __restrict__ W2, const float* __restrict__ B2,
           const float* __restrict__ W3, const float* __restrict__ B3,
           float* __restrict__ out_x)
{
    extern __shared__ float sw[];
    float* sW1 = sw;
    float* sb1 = sW1 + 19 * 64;
    float* sW2 = sb1 + 64;
    float* sb2 = sW2 + 4096;
    float* sW3 = sb2 + 64;
    float* sb3 = sW3 + 8192;

    const int tid = threadIdx.x;
    for (int i = tid; i < 19 * 64; i += 256) sW1[i] = W1[i];
    for (int i = tid; i < 64;      i += 256) sb1[i] = B1[i];
    for (int i = tid; i < 64 * 64; i += 256) sW2[i] = W2[i];
    for (int i = tid; i < 64;      i += 256) sb2[i] = B2[i];
    for (int i = tid; i < 64 * 128; i += 256) sW3[i] = W3[i];
    for (int i = tid; i < 128;     i += 256) sb3[i] = B3[i];
    __syncthreads();

    const int lane = tid & 31;
    const int c    = blockIdx.x * 8 + (tid >> 5);
    const int b    = c >> 12;
    const int s    = c & (SS - 1);

    const float cx = g_centers[c * 3 + 0];
    const float cy = g_centers[c * 3 + 1];
    const float cz = g_centers[c * 3 + 2];
    const float ccomp = (lane == 16) ? cx : ((lane == 17) ? cy : cz);
    const int cnt = g_cnt[c];

    float m0 = -3.0e38f, m1 = -3.0e38f, m2 = -3.0e38f, m3 = -3.0e38f;

    auto process4 = [&](const int rows[4], int nv) {
        float fv[4];
#pragma unroll
        for (int e = 0; e < 4; e++) {
            int r = rows[e];
            float v = 0.f;
            if (lane < FIN)          v = x[(size_t)r * FIN + lane];
            else if (lane < FIN + 3) v = pos[(size_t)r * 3 + (lane - FIN)] - ccomp;
            fv[e] = (e < nv) ? v : 0.f;
        }
        float a0[4], a1[4];
#pragma unroll
        for (int e = 0; e < 4; e++) { a0[e] = sb1[lane]; a1[e] = sb1[lane + 32]; }
#pragma unroll
        for (int i = 0; i < FIN + 3; i++) {
            float w0 = sW1[i * 64 + lane];
            float w1 = sW1[i * 64 + 32 + lane];
#pragma unroll
            for (int e = 0; e < 4; e++) {
                float v = __shfl_sync(0xffffffffu, fv[e], i);
                a0[e] = fmaf(v, w0, a0[e]);
                a1[e] = fmaf(v, w1, a1[e]);
            }
        }
#pragma unroll
        for (int e = 0; e < 4; e++) { a0[e] = fmaxf(a0[e], 0.f); a1[e] = fmaxf(a1[e], 0.f); }

        float g0[4], g1[4];
#pragma unroll
        for (int e = 0; e < 4; e++) { g0[e] = sb2[lane]; g1[e] = sb2[lane + 32]; }
#pragma unroll
        for (int i = 0; i < 64; i++) {
            float w0 = sW2[i * 64 + lane];
            float w1 = sW2[i * 64 + 32 + lane];
#pragma unroll
            for (int e = 0; e < 4; e++) {
                float v = (i < 32) ? __shfl_sync(0xffffffffu, a0[e], i)
                                   : __shfl_sync(0xffffffffu, a1[e], i - 32);
                g0[e] = fmaf(v, w0, g0[e]);
                g1[e] = fmaf(v, w1, g1[e]);
            }
        }
#pragma unroll
        for (int e = 0; e < 4; e++) { g0[e] = fmaxf(g0[e], 0.f); g1[e] = fmaxf(g1[e], 0.f); }

        float h0[4], h1v[4], h2v[4], h3v[4];
#pragma unroll
        for (int e = 0; e < 4; e++) {
            h0[e]  = sb3[lane];       h1v[e] = sb3[lane + 32];
            h2v[e] = sb3[lane + 64];  h3v[e] = sb3[lane + 96];
        }
#pragma unroll
        for (int i = 0; i < 64; i++) {
            float w0 = sW3[i * 128 + lane];
            float w1 = sW3[i * 128 + 32 + lane];
            float w2 = sW3[i * 128 + 64 + lane];
            float w3 = sW3[i * 128 + 96 + lane];
#pragma unroll
            for (int e = 0; e < 4; e++) {
                float v = (i < 32) ? __shfl_sync(0xffffffffu, g0[e], i)
                                   : __shfl_sync(0xffffffffu, g1[e], i - 32);
                h0[e]  = fmaf(v, w0, h0[e]);
                h1v[e] = fmaf(v, w1, h1v[e]);
                h2v[e] = fmaf(v, w2, h2v[e]);
                h3v[e] = fmaf(v, w3, h3v[e]);
            }
        }
#pragma unroll
        for (int e = 0; e < 4; e++) {
            if (e < nv) {
                m0 = fmaxf(m0, h0[e]);  m1 = fmaxf(m1, h1v[e]);
                m2 = fmaxf(m2, h2v[e]); m3 = fmaxf(m3, h3v[e]);
            }
        }
    };

    for (int eb = 0; eb < cnt; eb += 4) {
        int nv = min(4, cnt - eb);
        int rows[4];
#pragma unroll
        for (int e = 0; e < 4; e++) {
            int kk = eb + ((e < nv) ? e : 0);
            rows[e] = b * NN + g_nbr[c * KK + kk];
        }
        process4(rows, nv);
    }
    {
        int dflat = b * SS + s;
        int rows[4] = { dflat, dflat, dflat, dflat };
        process4(rows, 1);
    }

    out_x[(size_t)c * HOUT + lane]      = m0;
    out_x[(size_t)c * HOUT + lane + 32] = m1;
    out_x[(size_t)c * HOUT + lane + 64] = m2;
    out_x[(size_t)c * HOUT + lane + 96] = m3;
}

// ===========================================================================
// launch
// ===========================================================================
extern "C" void kernel_launch(void* const* d_in, const int* in_sizes, int n_in,
                              void* d_out, int out_size)
{
    const float* x   = (const float*)d_in[0];
    const float* pos = (const float*)d_in[1];
    const float* W1 = (const float*)d_in[3];
    const float* B1 = (const float*)d_in[4];
    const float* W2 = (const float*)d_in[5];
    const float* B2 = (const float*)d_in[6];
    const float* W3 = (const float*)d_in[7];
    const float* B3 = (const float*)d_in[8];

    float* out_x = (float*)d_out;
    float* out_c = out_x + (size_t)BB * SS * HOUT;
    float* out_b = out_c + (size_t)BB * SS * 3;

    const size_t fps_smem = (size_t)3 * NN * sizeof(float);   // 192 KB dynamic
    const size_t mlp_smem = (size_t)13760 * sizeof(float);
    cudaFuncSetAttribute(fps_kernel, cudaFuncAttributeMaxDynamicSharedMemorySize, (int)fps_smem);
    cudaFuncSetAttribute(mlp_kernel, cudaFuncAttributeMaxDynamicSharedMemorySize, (int)mlp_smem);

    init_hist_kernel<<<(BB * NCELL + 255) / 256, 256>>>();
    cell_count_kernel<<<(BB * NN + 255) / 256, 256>>>(pos);
    cell_scan_kernel<<<BB, NCELL>>>();
    cell_scatter_kernel<<<(BB * NN + 255) / 256, 256>>>(pos);
    fps_kernel<<<BB, 512, fps_smem>>>(pos, out_c);
    ballq_kernel<<<(BB * SS * 32) / 256, 256>>>(pos, out_b);
    mlp_kernel<<<(BB * SS) / 8, 256, mlp_smem>>>(x, pos, W1, B1, W2, B2, W3, B3, out_x);
}

// round 9
// speedup vs baseline: 1.9566x; 1.1417x over previous
#include <cuda_runtime.h>
#include <cstdint>

// ---------------------------------------------------------------------------
// SetAbstraction (PointNet++): FPS -> ball query -> MLP -> max
// B=2, N=16384, S=4096, K=32, F_IN=16, hidden 64-64-128
// Round 9 FPS: R8 (packed-identity REDUX) + single barrier per iteration:
//   double-buffered per-warp partials (parity t&1), redundant final argmax in
//   ALL warps, center carried in registers. Max warp skew = 1 iteration;
//   parities keep reader/writer sets disjoint.
// Selection sequence bit-identical to the naive scan.
// ---------------------------------------------------------------------------

#define BB   2
#define NN   16384
#define SS   4096
#define KK   32
#define FIN  16
#define HOUT 128
#define GC    8
#define NCELL 512
#define CW    0.125f
#define FULLM 0xffffffffu

// ---- scratch (__device__ globals; no allocation allowed) -------------------
__device__ float g_centers[BB * SS * 3];
__device__ int   g_nbr[BB * SS * KK];
__device__ int   g_cnt[BB * SS];

__device__ float2 g_sxy[BB * NN];      // sorted (x,y)
__device__ int2   g_szi[BB * NN];      // sorted (z bits, orig idx)
__device__ int    g_hist[BB * NCELL];
__device__ int    g_cstart[BB * (NCELL + 1)];
__device__ int    g_fill[BB * NCELL];

__device__ __forceinline__ int cell_of(float x, float y, float z) {
    int ix = (int)(x * (float)GC); ix = ix < 0 ? 0 : (ix > GC - 1 ? GC - 1 : ix);
    int iy = (int)(y * (float)GC); iy = iy < 0 ? 0 : (iy > GC - 1 ? GC - 1 : iy);
    int iz = (int)(z * (float)GC); iz = iz < 0 ? 0 : (iz > GC - 1 ? GC - 1 : iz);
    return (iz * GC + iy) * GC + ix;
}

// ===========================================================================
// Preprocessing: histogram -> scan -> scatter (counting sort by cell)
// ===========================================================================
__global__ void init_hist_kernel() {
    int i = blockIdx.x * blockDim.x + threadIdx.x;
    if (i < BB * NCELL) g_hist[i] = 0;
}

__global__ void cell_count_kernel(const float* __restrict__ pos) {
    int i = blockIdx.x * blockDim.x + threadIdx.x;
    if (i >= BB * NN) return;
    int b = i >> 14;
    float x = pos[(size_t)i * 3 + 0], y = pos[(size_t)i * 3 + 1], z = pos[(size_t)i * 3 + 2];
    atomicAdd(&g_hist[b * NCELL + cell_of(x, y, z)], 1);
}

__global__ void cell_scan_kernel() {
    __shared__ int sh[NCELL];
    __shared__ int ss[NCELL + 1];
    int b = blockIdx.x, tid = threadIdx.x;
    if (tid < NCELL) sh[tid] = g_hist[b * NCELL + tid];
    __syncthreads();
    if (tid == 0) {
        int acc = 0;
        for (int c = 0; c < NCELL; c++) { ss[c] = acc; acc += sh[c]; }
        ss[NCELL] = acc;
    }
    __syncthreads();
    if (tid < NCELL) {
        g_cstart[b * (NCELL + 1) + tid] = ss[tid];
        g_fill[b * NCELL + tid] = ss[tid];
    }
    if (tid == 0) g_cstart[b * (NCELL + 1) + NCELL] = ss[NCELL];
}

__global__ void cell_scatter_kernel(const float* __restrict__ pos) {
    int i = blockIdx.x * blockDim.x + threadIdx.x;
    if (i >= BB * NN) return;
    int b = i >> 14;
    int li = i & (NN - 1);
    float x = pos[(size_t)i * 3 + 0], y = pos[(size_t)i * 3 + 1], z = pos[(size_t)i * 3 + 2];
    int c = cell_of(x, y, z);
    int p = atomicAdd(&g_fill[b * NCELL + c], 1);
    g_sxy[b * NN + p] = make_float2(x, y);
    g_szi[b * NN + p] = make_int2(__float_as_int(z), li);
}

// ===========================================================================
// Kernel 1: grid-pruned exact FPS. One block per batch, 512 threads (16 warps).
// Warp w owns cells {w + 16*l}; lane l caches cell key (kv, kcand, kz) in regs.
// Per-lane scan key u64 = (dmin_bits<<28)|(~origidx&0x3fff)<<14|sorted_pos.
// ONE __syncthreads per iteration (double-buffered partials).
// ===========================================================================
__global__ void __launch_bounds__(512, 1)
fps_kernel(const float* __restrict__ pos, float* __restrict__ out_centers)
{
    extern __shared__ float sm[];
    float2* s_xy   = (float2*)sm;        // NN float2 (128 KB)
    float*  s_dmin = sm + 2 * NN;        // NN floats (64 KB)

    __shared__ unsigned long long s_part[2][16];  // parity-buffered partials
    __shared__ float              s_pz[2][16];    // parity-buffered winner z

    const int b = blockIdx.x, tid = threadIdx.x;
    const int w = tid >> 5, lane = tid & 31;
    const int base = b * NN;
    const int2* __restrict__ gz = g_szi + base;

    for (int p = tid; p < NN; p += 512) {
        s_xy[p] = g_sxy[base + p];
        s_dmin[p] = 1e10f;
    }
    if (tid < 16) {
        s_part[0][tid] = 0ULL; s_part[1][tid] = 0ULL;
        s_pz[0][tid] = 0.f;    s_pz[1][tid] = 0.f;
    }

    // this lane's owned cell
    const int cell = w + (lane << 4);
    const int cs0 = g_cstart[b * (NCELL + 1) + cell];
    const int cs1 = g_cstart[b * (NCELL + 1) + cell + 1];
    const int ix = cell & 7, iy = (cell >> 3) & 7, iz = cell >> 6;
    const float lox = (float)ix * CW - 1e-5f, hix = (float)ix * CW + CW + 1e-5f;
    const float loy = (float)iy * CW - 1e-5f, hiy = (float)iy * CW + CW + 1e-5f;
    const float loz = (float)iz * CW - 1e-5f, hiz = (float)iz * CW + CW + 1e-5f;

    unsigned kv    = __float_as_uint(1e10f);   // cached cell key: max dmin bits
    unsigned kcand = 0u;                       // (lo14<<14)|p of winner
    float    kz    = 0.f;                      // winner z

    // initial center (deterministic start at original point 0), in registers
    float cx = pos[(size_t)base * 3 + 0];
    float cy = pos[(size_t)base * 3 + 1];
    float cz = pos[(size_t)base * 3 + 2];
    if (tid == 0) {
        int row = b * SS;
        out_centers[row * 3 + 0] = cx; out_centers[row * 3 + 1] = cy; out_centers[row * 3 + 2] = cz;
        g_centers[row * 3 + 0]   = cx; g_centers[row * 3 + 1]   = cy; g_centers[row * 3 + 2]   = cz;
    }
    __syncthreads();

    for (int t = 1; t < SS; t++) {
        const int par = t & 1;

        // --- prune: each lane checks its own cell --------------------------
        float pdx = fmaxf(fmaxf(lox - cx, cx - hix), 0.f);
        float pdy = fmaxf(fmaxf(loy - cy, cy - hiy), 0.f);
        float pdz = fmaxf(fmaxf(loz - cz, cz - hiz), 0.f);
        float lb  = (pdx * pdx + pdy * pdy + pdz * pdz) * 0.999f;
        bool touched = lb < __uint_as_float(kv);
        unsigned tmask = __ballot_sync(FULLM, touched);

        if (tmask) {
            // --- process touched cells (pipelined next-cell preload) -------
            int j = __ffs(tmask) - 1; tmask &= tmask - 1;
            int st = __shfl_sync(FULLM, cs0, j);
            int en = __shfl_sync(FULLM, cs1, j);
            int p0v = st + lane; bool v = p0v < en;
            int2 zi = make_int2(0, 0); float2 xy = make_float2(0.f, 0.f);
            if (v) { zi = gz[p0v]; xy = s_xy[p0v]; }
            if (st + 32 + lane < en) {
                const int2* pf = &gz[st + 32 + lane];
                asm volatile("prefetch.global.L1 [%0];" :: "l"(pf));
            }
            while (j >= 0) {
                unsigned long long best = 0ULL; float bz = 0.f;
                if (v) {
                    int p = st + lane;
                    float zz  = __int_as_float(zi.x);
                    float ddx = __fsub_rn(xy.x, cx);
                    float ddy = __fsub_rn(xy.y, cy);
                    float ddz = __fsub_rn(zz,   cz);
                    float d   = __fadd_rn(__fadd_rn(__fmul_rn(ddx, ddx), __fmul_rn(ddy, ddy)),
                                          __fmul_rn(ddz, ddz));
                    float dm  = fminf(s_dmin[p], d);
                    s_dmin[p] = dm;
                    unsigned lo14 = (~(unsigned)zi.y) & 0x3fffu;
                    best = (((unsigned long long)__float_as_uint(dm)) << 28)
                         | ((unsigned long long)lo14 << 14)
                         | (unsigned long long)p;
                    bz = zz;
                }
                // prefetch next touched cell's first chunk
                int jn = -1, stn = 0, enn = 0; bool vn = false;
                int2 zin = make_int2(0, 0); float2 xyn = make_float2(0.f, 0.f);
                if (tmask) {
                    jn = __ffs(tmask) - 1; tmask &= tmask - 1;
                    stn = __shfl_sync(FULLM, cs0, jn);
                    enn = __shfl_sync(FULLM, cs1, jn);
                    int p = stn + lane; vn = p < enn;
                    if (vn) { zin = gz[p]; xyn = s_xy[p]; }
                    if (stn + 32 + lane < enn) {
                        const int2* pf = &gz[stn + 32 + lane];
                        asm volatile("prefetch.global.L1 [%0];" :: "l"(pf));
                    }
                }
                // remaining chunks of current cell
                for (int pp = st + 32; pp < en; pp += 32) {
                    int p = pp + lane;
                    if (p < en) {
                        int2   z2 = gz[p];
                        float2 x2 = s_xy[p];
                        float zz  = __int_as_float(z2.x);
                        float ddx = __fsub_rn(x2.x, cx);
                        float ddy = __fsub_rn(x2.y, cy);
                        float ddz = __fsub_rn(zz,   cz);
                        float d   = __fadd_rn(__fadd_rn(__fmul_rn(ddx, ddx), __fmul_rn(ddy, ddy)),
                                              __fmul_rn(ddz, ddz));
                        float dm  = fminf(s_dmin[p], d);
                        s_dmin[p] = dm;
                        unsigned lo14 = (~(unsigned)z2.y) & 0x3fffu;
                        unsigned long long pk =
                            (((unsigned long long)__float_as_uint(dm)) << 28)
                            | ((unsigned long long)lo14 << 14)
                            | (unsigned long long)p;
                        if (pk > best) { best = pk; bz = zz; }
                    }
                }
                // cell key via packed REDUX (identity rides in the value)
                unsigned du    = (unsigned)(best >> 28);
                unsigned wm    = __reduce_max_sync(FULLM, du);
                unsigned cand  = (du == wm) ? (unsigned)(best & 0xFFFFFFFull) : 0u;
                unsigned mcand = __reduce_max_sync(FULLM, cand);
                int wp  = (int)(mcand & 0x3fffu);
                int src = (wp - st) & 31;
                float zw = __shfl_sync(FULLM, bz, src);
                if (lane == j) { kv = wm; kcand = mcand; kz = zw; }
                j = jn; st = stn; en = enn; v = vn; zi = zin; xy = xyn;
            }

            // per-warp partial over its 32 owned cells -> parity buffer
            unsigned mv  = __reduce_max_sync(FULLM, kv);
            unsigned c2  = (kv == mv) ? kcand : 0u;
            unsigned mc2 = __reduce_max_sync(FULLM, c2);
            if (kv == mv && kcand == mc2) {   // unique (mc2 embeds unique p)
                s_part[par][w] = (((unsigned long long)mv) << 32) | mc2;
                s_pz[par][w]   = kz;
            }
        } else {
            // untouched warp: partial unchanged; copy across parity
            if (lane == 0) {
                s_part[par][w] = s_part[par ^ 1][w];
                s_pz[par][w]   = s_pz[par ^ 1][w];
            }
        }
        __syncthreads();   // the ONLY barrier per iteration

        // --- redundant final argmax over 16 partials (every warp) ----------
        unsigned long long pk = (lane < 16) ? s_part[par][lane] : 0ULL;
        float pz = (lane < 16) ? s_pz[par][lane] : 0.f;
        unsigned hi = (unsigned)(pk >> 32), lo = (unsigned)pk;
        unsigned mv2 = __reduce_max_sync(FULLM, hi);
        unsigned c3  = (hi == mv2) ? lo : 0u;
        unsigned mc3 = __reduce_max_sync(FULLM, c3);
        unsigned bm  = __ballot_sync(FULLM, (hi == mv2) && (lo == mc3));
        int src = __ffs(bm) - 1;
        int wp  = (int)(mc3 & 0x3fffu);
        float zw = __shfl_sync(FULLM, pz, src);
        float2 xyw = s_xy[wp];                 // broadcast LDS
        cx = xyw.x; cy = xyw.y; cz = zw;       // next center, in registers
        if (w == 0 && lane == src) {
            int row = b * SS + t;
            out_centers[row * 3 + 0] = cx; out_centers[row * 3 + 1] = cy; out_centers[row * 3 + 2] = cz;
            g_centers[row * 3 + 0]   = cx; g_centers[row * 3 + 1]   = cy; g_centers[row * 3 + 2]   = cz;
        }
    }
}

// ===========================================================================
// Kernel 2: Ball query — one warp per center; ordered scan, first K within R.
// ===========================================================================
__global__ void __launch_bounds__(256, 8)
ballq_kernel(const float* __restrict__ pos, float* __restrict__ out_batch)
{
    const int w    = (blockIdx.x * blockDim.x + threadIdx.x) >> 5;
    const int lane = threadIdx.x & 31;
    if (w >= BB * SS) return;

    const int b = w >> 12;
    const int s = w & (SS - 1);
    const float* pb = pos + (size_t)b * NN * 3;

    const float cx = g_centers[w * 3 + 0];
    const float cy = g_centers[w * 3 + 1];
    const float cz = g_centers[w * 3 + 2];
    const float R2 = (float)(0.1 * 0.1);
    const int excl = s - b * (NN - SS);

    int cnt = 0;
    for (int j0 = 0; j0 < NN && cnt < KK; j0 += 32) {
        int j = j0 + lane;
        float x_ = pb[j * 3 + 0];
        float y_ = pb[j * 3 + 1];
        float z_ = pb[j * 3 + 2];
        float dx = __fsub_rn(cx, x_);
        float dy = __fsub_rn(cy, y_);
        float dz = __fsub_rn(cz, z_);
        float d2 = __fadd_rn(__fadd_rn(__fmul_rn(dx, dx), __fmul_rn(dy, dy)),
                             __fmul_rn(dz, dz));
        bool hit = (d2 <= R2) && (j != excl);
        unsigned m = __ballot_sync(0xffffffffu, hit);
        while (m && cnt < KK) {
            int bit = __ffs(m) - 1;
            if (lane == bit) g_nbr[w * KK + cnt] = j0 + bit;
            cnt++;
            m &= m - 1;
        }
    }
    if (lane == 0) {
        g_cnt[w] = cnt;
        out_batch[w] = (float)b;
    }
}

// ===========================================================================
// Kernel 3: gather + MLP(19->64->64->128) + max over K+1 (unchanged).
// ===========================================================================
__global__ void __launch_bounds__(256, 1)
mlp_kernel(const float* __restrict__ x, const float* __restrict__ pos,
           const float* __restrict__ W1, const float* __restrict__ B1,
           const float* __restrict__ W2, const float* __restrict__ B2,
           const float* __restrict__ W3, const float* __restrict__ B3,
           float* __restrict__ out_x)
{
    extern __shared__ float sw[];
    float* sW1 = sw;
    float* sb1 = sW1 + 19 * 64;
    float* sW2 = sb1 + 64;
    float* sb2 = sW2 + 4096;
    float* sW3 = sb2 + 64;
    float* sb3 = sW3 + 8192;

    const int tid = threadIdx.x;
    for (int i = tid; i < 19 * 64; i += 256) sW1[i] = W1[i];
    for (int i = tid; i < 64;      i += 256) sb1[i] = B1[i];
    for (int i = tid; i < 64 * 64; i += 256) sW2[i] = W2[i];
    for (int i = tid; i < 64;      i += 256) sb2[i] = B2[i];
    for (int i = tid; i < 64 * 128; i += 256) sW3[i] = W3[i];
    for (int i = tid; i < 128;     i += 256) sb3[i] = B3[i];
    __syncthreads();

    const int lane = tid & 31;
    const int c    = blockIdx.x * 8 + (tid >> 5);
    const int b    = c >> 12;
    const int s    = c & (SS - 1);

    const float cx = g_centers[c * 3 + 0];
    const float cy = g_centers[c * 3 + 1];
    const float cz = g_centers[c * 3 + 2];
    const float ccomp = (lane == 16) ? cx : ((lane == 17) ? cy : cz);
    const int cnt = g_cnt[c];

    float m0 = -3.0e38f, m1 = -3.0e38f, m2 = -3.0e38f, m3 = -3.0e38f;

    auto process4 = [&](const int rows[4], int nv) {
        float fv[4];
#pragma unroll
        for (int e = 0; e < 4; e++) {
            int r = rows[e];
            float v = 0.f;
            if (lane < FIN)          v = x[(size_t)r * FIN + lane];
            else if (lane < FIN + 3) v = pos[(size_t)r * 3 + (lane - FIN)] - ccomp;
            fv[e] = (e < nv) ? v : 0.f;
        }
        float a0[4], a1[4];
#pragma unroll
        for (int e = 0; e < 4; e++) { a0[e] = sb1[lane]; a1[e] = sb1[lane + 32]; }
#pragma unroll
        for (int i = 0; i < FIN + 3; i++) {
            float w0 = sW1[i * 64 + lane];
            float w1 = sW1[i * 64 + 32 + lane];
#pragma unroll
            for (int e = 0; e < 4; e++) {
                float v = __shfl_sync(0xffffffffu, fv[e], i);
                a0[e] = fmaf(v, w0, a0[e]);
                a1[e] = fmaf(v, w1, a1[e]);
            }
        }
#pragma unroll
        for (int e = 0; e < 4; e++) { a0[e] = fmaxf(a0[e], 0.f); a1[e] = fmaxf(a1[e], 0.f); }

        float g0[4], g1[4];
#pragma unroll
        for (int e = 0; e < 4; e++) { g0[e] = sb2[lane]; g1[e] = sb2[lane + 32]; }
#pragma unroll
        for (int i = 0; i < 64; i++) {
            float w0 = sW2[i * 64 + lane];
            float w1 = sW2[i * 64 + 32 + lane];
#pragma unroll
            for (int e = 0; e < 4; e++) {
                float v = (i < 32) ? __shfl_sync(0xffffffffu, a0[e], i)
                                   : __shfl_sync(0xffffffffu, a1[e], i - 32);
                g0[e] = fmaf(v, w0, g0[e]);
                g1[e] = fmaf(v, w1, g1[e]);
            }
        }
#pragma unroll
        for (int e = 0; e < 4; e++) { g0[e] = fmaxf(g0[e], 0.f); g1[e] = fmaxf(g1[e], 0.f); }

        float h0[4], h1v[4], h2v[4], h3v[4];
#pragma unroll
        for (int e = 0; e < 4; e++) {
            h0[e]  = sb3[lane];       h1v[e] = sb3[lane + 32];
            h2v[e] = sb3[lane + 64];  h3v[e] = sb3[lane + 96];
        }
#pragma unroll
        for (int i = 0; i < 64; i++) {
            float w0 = sW3[i * 128 + lane];
            float w1 = sW3[i * 128 + 32 + lane];
            float w2 = sW3[i * 128 + 64 + lane];
            float w3 = sW3[i * 128 + 96 + lane];
#pragma unroll
            for (int e = 0; e < 4; e++) {
                float v = (i < 32) ? __shfl_sync(0xffffffffu, g0[e], i)
                                   : __shfl_sync(0xffffffffu, g1[e], i - 32);
                h0[e]  = fmaf(v, w0, h0[e]);
                h1v[e] = fmaf(v, w1, h1v[e]);
                h2v[e] = fmaf(v, w2, h2v[e]);
                h3v[e] = fmaf(v, w3, h3v[e]);
            }
        }
#pragma unroll
        for (int e = 0; e < 4; e++) {
            if (e < nv) {
                m0 = fmaxf(m0, h0[e]);  m1 = fmaxf(m1, h1v[e]);
                m2 = fmaxf(m2, h2v[e]); m3 = fmaxf(m3, h3v[e]);
            }
        }
    };

    for (int eb = 0; eb < cnt; eb += 4) {
        int nv = min(4, cnt - eb);
        int rows[4];
#pragma unroll
        for (int e = 0; e < 4; e++) {
            int kk = eb + ((e < nv) ? e : 0);
            rows[e] = b * NN + g_nbr[c * KK + kk];
        }
        process4(rows, nv);
    }
    {
        int dflat = b * SS + s;
        int rows[4] = { dflat, dflat, dflat, dflat };
        process4(rows, 1);
    }

    out_x[(size_t)c * HOUT + lane]      = m0;
    out_x[(size_t)c * HOUT + lane + 32] = m1;
    out_x[(size_t)c * HOUT + lane + 64] = m2;
    out_x[(size_t)c * HOUT + lane + 96] = m3;
}

// ===========================================================================
// launch
// ===========================================================================
extern "C" void kernel_launch(void* const* d_in, const int* in_sizes, int n_in,
                              void* d_out, int out_size)
{
    const float* x   = (const float*)d_in[0];
    const float* pos = (const float*)d_in[1];
    const float* W1 = (const float*)d_in[3];
    const float* B1 = (const float*)d_in[4];
    const float* W2 = (const float*)d_in[5];
    const float* B2 = (const float*)d_in[6];
    const float* W3 = (const float*)d_in[7];
    const float* B3 = (const float*)d_in[8];

    float* out_x = (float*)d_out;
    float* out_c = out_x + (size_t)BB * SS * HOUT;
    float* out_b = out_c + (size_t)BB * SS * 3;

    const size_t fps_smem = (size_t)3 * NN * sizeof(float);   // 192 KB dynamic
    const size_t mlp_smem = (size_t)13760 * sizeof(float);
    cudaFuncSetAttribute(fps_kernel, cudaFuncAttributeMaxDynamicSharedMemorySize, (int)fps_smem);
    cudaFuncSetAttribute(mlp_kernel, cudaFuncAttributeMaxDynamicSharedMemorySize, (int)mlp_smem);

    init_hist_kernel<<<(BB * NCELL + 255) / 256, 256>>>();
    cell_count_kernel<<<(BB * NN + 255) / 256, 256>>>(pos);
    cell_scan_kernel<<<BB, NCELL>>>();
    cell_scatter_kernel<<<(BB * NN + 255) / 256, 256>>>(pos);
    fps_kernel<<<BB, 512, fps_smem>>>(pos, out_c);
    ballq_kernel<<<(BB * SS * 32) / 256, 256>>>(pos, out_b);
    mlp_kernel<<<(BB * SS) / 8, 256, mlp_smem>>>(x, pos, W1, B1, W2, B2, W3, B3, out_x);
}

// round 10
// speedup vs baseline: 2.2974x; 1.1742x over previous
#include <cuda_runtime.h>
#include <cstdint>

// ---------------------------------------------------------------------------
// SetAbstraction (PointNet++): FPS -> ball query -> MLP -> max
// B=2, N=16384, S=4096, K=32, F_IN=16, hidden 64-64-128
// Round 10 FPS: R9 (packed REDUX, single barrier, register center) +
//   - XOR cell->warp bijection (z-adjacent cells on different warps;
//     evens out the slowest-warp scan the barrier waits on)
//   - z recovered via one uniform L1-hot LDG at the final reduce
//     (per-cell z shuffles, final ballot/shuffles, s_pz all deleted)
// Selection sequence bit-identical to the naive scan.
// ---------------------------------------------------------------------------

#define BB   2
#define NN   16384
#define SS   4096
#define KK   32
#define FIN  16
#define HOUT 128
#define GC    8
#define NCELL 512
#define CW    0.125f
#define FULLM 0xffffffffu

// ---- scratch (__device__ globals; no allocation allowed) -------------------
__device__ float g_centers[BB * SS * 3];
__device__ int   g_nbr[BB * SS * KK];
__device__ int   g_cnt[BB * SS];

__device__ float2 g_sxy[BB * NN];      // sorted (x,y)
__device__ int2   g_szi[BB * NN];      // sorted (z bits, orig idx)
__device__ int    g_hist[BB * NCELL];
__device__ int    g_cstart[BB * (NCELL + 1)];
__device__ int    g_fill[BB * NCELL];

__device__ __forceinline__ int cell_of(float x, float y, float z) {
    int ix = (int)(x * (float)GC); ix = ix < 0 ? 0 : (ix > GC - 1 ? GC - 1 : ix);
    int iy = (int)(y * (float)GC); iy = iy < 0 ? 0 : (iy > GC - 1 ? GC - 1 : iy);
    int iz = (int)(z * (float)GC); iz = iz < 0 ? 0 : (iz > GC - 1 ? GC - 1 : iz);
    return (iz * GC + iy) * GC + ix;
}

// ===========================================================================
// Preprocessing: histogram -> scan -> scatter (counting sort by cell)
// ===========================================================================
__global__ void init_hist_kernel() {
    int i = blockIdx.x * blockDim.x + threadIdx.x;
    if (i < BB * NCELL) g_hist[i] = 0;
}

__global__ void cell_count_kernel(const float* __restrict__ pos) {
    int i = blockIdx.x * blockDim.x + threadIdx.x;
    if (i >= BB * NN) return;
    int b = i >> 14;
    float x = pos[(size_t)i * 3 + 0], y = pos[(size_t)i * 3 + 1], z = pos[(size_t)i * 3 + 2];
    atomicAdd(&g_hist[b * NCELL + cell_of(x, y, z)], 1);
}

__global__ void cell_scan_kernel() {
    __shared__ int sh[NCELL];
    __shared__ int ss[NCELL + 1];
    int b = blockIdx.x, tid = threadIdx.x;
    if (tid < NCELL) sh[tid] = g_hist[b * NCELL + tid];
    __syncthreads();
    if (tid == 0) {
        int acc = 0;
        for (int c = 0; c < NCELL; c++) { ss[c] = acc; acc += sh[c]; }
        ss[NCELL] = acc;
    }
    __syncthreads();
    if (tid < NCELL) {
        g_cstart[b * (NCELL + 1) + tid] = ss[tid];
        g_fill[b * NCELL + tid] = ss[tid];
    }
    if (tid == 0) g_cstart[b * (NCELL + 1) + NCELL] = ss[NCELL];
}

__global__ void cell_scatter_kernel(const float* __restrict__ pos) {
    int i = blockIdx.x * blockDim.x + threadIdx.x;
    if (i >= BB * NN) return;
    int b = i >> 14;
    int li = i & (NN - 1);
    float x = pos[(size_t)i * 3 + 0], y = pos[(size_t)i * 3 + 1], z = pos[(size_t)i * 3 + 2];
    int c = cell_of(x, y, z);
    int p = atomicAdd(&g_fill[b * NCELL + c], 1);
    g_sxy[b * NN + p] = make_float2(x, y);
    g_szi[b * NN + p] = make_int2(__float_as_int(z), li);
}

// ===========================================================================
// Kernel 1: grid-pruned exact FPS. One block per batch, 512 threads (16 warps).
// Cell assignment: p = w + 16*lane, cell = p ^ ((p>>6)*9)  (XOR bijection;
// z-adjacent cells land on different warps). Per-lane cached key in regs.
// Per-lane scan key u64 = (dmin_bits<<28)|(~origidx&0x3fff)<<14|sorted_pos.
// ONE __syncthreads per iteration (double-buffered partials).
// ===========================================================================
__global__ void __launch_bounds__(512, 1)
fps_kernel(const float* __restrict__ pos, float* __restrict__ out_centers)
{
    extern __shared__ float sm[];
    float2* s_xy   = (float2*)sm;        // NN float2 (128 KB)
    float*  s_dmin = sm + 2 * NN;        // NN floats (64 KB)

    __shared__ unsigned long long s_part[2][16];  // parity-buffered partials

    const int b = blockIdx.x, tid = threadIdx.x;
    const int w = tid >> 5, lane = tid & 31;
    const int base = b * NN;
    const int2* __restrict__ gz = g_szi + base;

    for (int p = tid; p < NN; p += 512) {
        s_xy[p] = g_sxy[base + p];
        s_dmin[p] = 1e10f;
    }
    if (tid < 16) { s_part[0][tid] = 0ULL; s_part[1][tid] = 0ULL; }

    // this lane's owned cell (XOR bijection spreads x, y AND z neighbors)
    const int pidx = w + (lane << 4);
    const int cell = pidx ^ ((pidx >> 6) * 9);
    const int cs0 = g_cstart[b * (NCELL + 1) + cell];
    const int cs1 = g_cstart[b * (NCELL + 1) + cell + 1];
    const int ix = cell & 7, iy = (cell >> 3) & 7, iz = cell >> 6;
    const float lox = (float)ix * CW - 1e-5f, hix = (float)ix * CW + CW + 1e-5f;
    const float loy = (float)iy * CW - 1e-5f, hiy = (float)iy * CW + CW + 1e-5f;
    const float loz = (float)iz * CW - 1e-5f, hiz = (float)iz * CW + CW + 1e-5f;

    unsigned kv    = __float_as_uint(1e10f);   // cached cell key: max dmin bits
    unsigned kcand = 0u;                       // (lo14<<14)|p of winner

    // initial center (deterministic start at original point 0), in registers
    float cx = pos[(size_t)base * 3 + 0];
    float cy = pos[(size_t)base * 3 + 1];
    float cz = pos[(size_t)base * 3 + 2];
    if (tid == 0) {
        int row = b * SS;
        out_centers[row * 3 + 0] = cx; out_centers[row * 3 + 1] = cy; out_centers[row * 3 + 2] = cz;
        g_centers[row * 3 + 0]   = cx; g_centers[row * 3 + 1]   = cy; g_centers[row * 3 + 2]   = cz;
    }
    __syncthreads();

    for (int t = 1; t < SS; t++) {
        const int par = t & 1;

        // --- prune: each lane checks its own cell --------------------------
        float pdx = fmaxf(fmaxf(lox - cx, cx - hix), 0.f);
        float pdy = fmaxf(fmaxf(loy - cy, cy - hiy), 0.f);
        float pdz = fmaxf(fmaxf(loz - cz, cz - hiz), 0.f);
        float lb  = (pdx * pdx + pdy * pdy + pdz * pdz) * 0.999f;
        bool touched = lb < __uint_as_float(kv);
        unsigned tmask = __ballot_sync(FULLM, touched);

        if (tmask) {
            // --- process touched cells (pipelined next-cell preload) -------
            int j = __ffs(tmask) - 1; tmask &= tmask - 1;
            int st = __shfl_sync(FULLM, cs0, j);
            int en = __shfl_sync(FULLM, cs1, j);
            int p0v = st + lane; bool v = p0v < en;
            int2 zi = make_int2(0, 0); float2 xy = make_float2(0.f, 0.f);
            if (v) { zi = gz[p0v]; xy = s_xy[p0v]; }
            if (st + 32 + lane < en) {
                const int2* pf = &gz[st + 32 + lane];
                asm volatile("prefetch.global.L1 [%0];" :: "l"(pf));
            }
            while (j >= 0) {
                unsigned long long best = 0ULL;
                if (v) {
                    int p = st + lane;
                    float zz  = __int_as_float(zi.x);
                    float ddx = __fsub_rn(xy.x, cx);
                    float ddy = __fsub_rn(xy.y, cy);
                    float ddz = __fsub_rn(zz,   cz);
                    float d   = __fadd_rn(__fadd_rn(__fmul_rn(ddx, ddx), __fmul_rn(ddy, ddy)),
                                          __fmul_rn(ddz, ddz));
                    float dm  = fminf(s_dmin[p], d);
                    s_dmin[p] = dm;
                    unsigned lo14 = (~(unsigned)zi.y) & 0x3fffu;
                    best = (((unsigned long long)__float_as_uint(dm)) << 28)
                         | ((unsigned long long)lo14 << 14)
                         | (unsigned long long)p;
                }
                // prefetch next touched cell's first chunk
                int jn = -1, stn = 0, enn = 0; bool vn = false;
                int2 zin = make_int2(0, 0); float2 xyn = make_float2(0.f, 0.f);
                if (tmask) {
                    jn = __ffs(tmask) - 1; tmask &= tmask - 1;
                    stn = __shfl_sync(FULLM, cs0, jn);
                    enn = __shfl_sync(FULLM, cs1, jn);
                    int p = stn + lane; vn = p < enn;
                    if (vn) { zin = gz[p]; xyn = s_xy[p]; }
                    if (stn + 32 + lane < enn) {
                        const int2* pf = &gz[stn + 32 + lane];
                        asm volatile("prefetch.global.L1 [%0];" :: "l"(pf));
                    }
                }
                // remaining chunks of current cell
                for (int pp = st + 32; pp < en; pp += 32) {
                    int p = pp + lane;
                    if (p < en) {
                        int2   z2 = gz[p];
                        float2 x2 = s_xy[p];
                        float zz  = __int_as_float(z2.x);
                        float ddx = __fsub_rn(x2.x, cx);
                        float ddy = __fsub_rn(x2.y, cy);
                        float ddz = __fsub_rn(zz,   cz);
                        float d   = __fadd_rn(__fadd_rn(__fmul_rn(ddx, ddx), __fmul_rn(ddy, ddy)),
                                              __fmul_rn(ddz, ddz));
                        float dm  = fminf(s_dmin[p], d);
                        s_dmin[p] = dm;
                        unsigned lo14 = (~(unsigned)z2.y) & 0x3fffu;
                        unsigned long long pk =
                            (((unsigned long long)__float_as_uint(dm)) << 28)
                            | ((unsigned long long)lo14 << 14)
                            | (unsigned long long)p;
                        if (pk > best) best = pk;
                    }
                }
                // cell key via packed REDUX (identity rides in the value)
                unsigned du    = (unsigned)(best >> 28);
                unsigned wm    = __reduce_max_sync(FULLM, du);
                unsigned cand  = (du == wm) ? (unsigned)(best & 0xFFFFFFFull) : 0u;
                unsigned mcand = __reduce_max_sync(FULLM, cand);
                if (lane == j) { kv = wm; kcand = mcand; }
                j = jn; st = stn; en = enn; v = vn; zi = zin; xy = xyn;
            }

            // per-warp partial over its 32 owned cells -> parity buffer
            unsigned mv  = __reduce_max_sync(FULLM, kv);
            unsigned c2  = (kv == mv) ? kcand : 0u;
            unsigned mc2 = __reduce_max_sync(FULLM, c2);
            if (kv == mv && kcand == mc2) {   // unique (mc2 embeds unique p)
                s_part[par][w] = (((unsigned long long)mv) << 32) | mc2;
            }
        } else {
            // untouched warp: partial unchanged; copy across parity
            if (lane == 0) s_part[par][w] = s_part[par ^ 1][w];
        }
        __syncthreads();   // the ONLY barrier per iteration

        // --- redundant final argmax over 16 partials (every warp) ----------
        unsigned long long pk = (lane < 16) ? s_part[par][lane] : 0ULL;
        unsigned hi = (unsigned)(pk >> 32), lo = (unsigned)pk;
        unsigned mv2 = __reduce_max_sync(FULLM, hi);
        unsigned c3  = (hi == mv2) ? lo : 0u;
        unsigned mc3 = __reduce_max_sync(FULLM, c3);
        int wp  = (int)(mc3 & 0x3fffu);
        float2 xyw = s_xy[wp];                       // broadcast LDS
        float  zw  = __int_as_float(gz[wp].x);       // uniform LDG, L1-hot
        cx = xyw.x; cy = xyw.y; cz = zw;             // next center, in regs
        if (w == 0 && hi == mv2 && lo == mc3) {      // unique winner lane
            int row = b * SS + t;
            out_centers[row * 3 + 0] = cx; out_centers[row * 3 + 1] = cy; out_centers[row * 3 + 2] = cz;
            g_centers[row * 3 + 0]   = cx; g_centers[row * 3 + 1]   = cy; g_centers[row * 3 + 2]   = cz;
        }
    }
}

// ===========================================================================
// Kernel 2: Ball query — one warp per center; ordered scan, first K within R.
// ===========================================================================
__global__ void __launch_bounds__(256, 8)
ballq_kernel(const float* __restrict__ pos, float* __restrict__ out_batch)
{
    const int w    = (blockIdx.x * blockDim.x + threadIdx.x) >> 5;
    const int lane = threadIdx.x & 31;
    if (w >= BB * SS) return;

    const int b = w >> 12;
    const int s = w & (SS - 1);
    const float* pb = pos + (size_t)b * NN * 3;

    const float cx = g_centers[w * 3 + 0];
    const float cy = g_centers[w * 3 + 1];
    const float cz = g_centers[w * 3 + 2];
    const float R2 = (float)(0.1 * 0.1);
    const int excl = s - b * (NN - SS);

    int cnt = 0;
    for (int j0 = 0; j0 < NN && cnt < KK; j0 += 32) {
        int j = j0 + lane;
        float x_ = pb[j * 3 + 0];
        float y_ = pb[j * 3 + 1];
        float z_ = pb[j * 3 + 2];
        float dx = __fsub_rn(cx, x_);
        float dy = __fsub_rn(cy, y_);
        float dz = __fsub_rn(cz, z_);
        float d2 = __fadd_rn(__fadd_rn(__fmul_rn(dx, dx), __fmul_rn(dy, dy)),
                             __fmul_rn(dz, dz));
        bool hit = (d2 <= R2) && (j != excl);
        unsigned m = __ballot_sync(0xffffffffu, hit);
        while (m && cnt < KK) {
            int bit = __ffs(m) - 1;
            if (lane == bit) g_nbr[w * KK + cnt] = j0 + bit;
            cnt++;
            m &= m - 1;
        }
    }
    if (lane == 0) {
        g_cnt[w] = cnt;
        out_batch[w] = (float)b;
    }
}

// ===========================================================================
// Kernel 3: gather + MLP(19->64->64->128) + max over K+1 (unchanged).
// ===========================================================================
__global__ void __launch_bounds__(256, 1)
mlp_kernel(const float* __restrict__ x, const float* __restrict__ pos,
           const float* __restrict__ W1, const float* __restrict__ B1,
           const float* __restrict__ W2, const float* __restrict__ B2,
           const float* __restrict__ W3, const float* __restrict__ B3,
           float* __restrict__ out_x)
{
    extern __shared__ float sw[];
    float* sW1 = sw;
    float* sb1 = sW1 + 19 * 64;
    float* sW2 = sb1 + 64;
    float* sb2 = sW2 + 4096;
    float* sW3 = sb2 + 64;
    float* sb3 = sW3 + 8192;

    const int tid = threadIdx.x;
    for (int i = tid; i < 19 * 64; i += 256) sW1[i] = W1[i];
    for (int i = tid; i < 64;      i += 256) sb1[i] = B1[i];
    for (int i = tid; i < 64 * 64; i += 256) sW2[i] = W2[i];
    for (int i = tid; i < 64;      i += 256) sb2[i] = B2[i];
    for (int i = tid; i < 64 * 128; i += 256) sW3[i] = W3[i];
    for (int i = tid; i < 128;     i += 256) sb3[i] = B3[i];
    __syncthreads();

    const int lane = tid & 31;
    const int c    = blockIdx.x * 8 + (tid >> 5);
    const int b    = c >> 12;
    const int s    = c & (SS - 1);

    const float cx = g_centers[c * 3 + 0];
    const float cy = g_centers[c * 3 + 1];
    const float cz = g_centers[c * 3 + 2];
    const float ccomp = (lane == 16) ? cx : ((lane == 17) ? cy : cz);
    const int cnt = g_cnt[c];

    float m0 = -3.0e38f, m1 = -3.0e38f, m2 = -3.0e38f, m3 = -3.0e38f;

    auto process4 = [&](const int rows[4], int nv) {
        float fv[4];
#pragma unroll
        for (int e = 0; e < 4; e++) {
            int r = rows[e];
            float v = 0.f;
            if (lane < FIN)          v = x[(size_t)r * FIN + lane];
            else if (lane < FIN + 3) v = pos[(size_t)r * 3 + (lane - FIN)] - ccomp;
            fv[e] = (e < nv) ? v : 0.f;
        }
        float a0[4], a1[4];
#pragma unroll
        for (int e = 0; e < 4; e++) { a0[e] = sb1[lane]; a1[e] = sb1[lane + 32]; }
#pragma unroll
        for (int i = 0; i < FIN + 3; i++) {
            float w0 = sW1[i * 64 + lane];
            float w1 = sW1[i * 64 + 32 + lane];
#pragma unroll
            for (int e = 0; e < 4; e++) {
                float v = __shfl_sync(0xffffffffu, fv[e], i);
                a0[e] = fmaf(v, w0, a0[e]);
                a1[e] = fmaf(v, w1, a1[e]);
            }
        }
#pragma unroll
        for (int e = 0; e < 4; e++) { a0[e] = fmaxf(a0[e], 0.f); a1[e] = fmaxf(a1[e], 0.f); }

        float g0[4], g1[4];
#pragma unroll
        for (int e = 0; e < 4; e++) { g0[e] = sb2[lane]; g1[e] = sb2[lane + 32]; }
#pragma unroll
        for (int i = 0; i < 64; i++) {
            float w0 = sW2[i * 64 + lane];
            float w1 = sW2[i * 64 + 32 + lane];
#pragma unroll
            for (int e = 0; e < 4; e++) {
                float v = (i < 32) ? __shfl_sync(0xffffffffu, a0[e], i)
                                   : __shfl_sync(0xffffffffu, a1[e], i - 32);
                g0[e] = fmaf(v, w0, g0[e]);
                g1[e] = fmaf(v, w1, g1[e]);
            }
        }
#pragma unroll
        for (int e = 0; e < 4; e++) { g0[e] = fmaxf(g0[e], 0.f); g1[e] = fmaxf(g1[e], 0.f); }

        float h0[4], h1v[4], h2v[4], h3v[4];
#pragma unroll
        for (int e = 0; e < 4; e++) {
            h0[e]  = sb3[lane];       h1v[e] = sb3[lane + 32];
            h2v[e] = sb3[lane + 64];  h3v[e] = sb3[lane + 96];
        }
#pragma unroll
        for (int i = 0; i < 64; i++) {
            float w0 = sW3[i * 128 + lane];
            float w1 = sW3[i * 128 + 32 + lane];
            float w2 = sW3[i * 128 + 64 + lane];
            float w3 = sW3[i * 128 + 96 + lane];
#pragma unroll
            for (int e = 0; e < 4; e++) {
                float v = (i < 32) ? __shfl_sync(0xffffffffu, g0[e], i)
                                   : __shfl_sync(0xffffffffu, g1[e], i - 32);
                h0[e]  = fmaf(v, w0, h0[e]);
                h1v[e] = fmaf(v, w1, h1v[e]);
                h2v[e] = fmaf(v, w2, h2v[e]);
                h3v[e] = fmaf(v, w3, h3v[e]);
            }
        }
#pragma unroll
        for (int e = 0; e < 4; e++) {
            if (e < nv) {
                m0 = fmaxf(m0, h0[e]);  m1 = fmaxf(m1, h1v[e]);
                m2 = fmaxf(m2, h2v[e]); m3 = fmaxf(m3, h3v[e]);
            }
        }
    };

    for (int eb = 0; eb < cnt; eb += 4) {
        int nv = min(4, cnt - eb);
        int rows[4];
#pragma unroll
        for (int e = 0; e < 4; e++) {
            int kk = eb + ((e < nv) ? e : 0);
            rows[e] = b * NN + g_nbr[c * KK + kk];
        }
        process4(rows, nv);
    }
    {
        int dflat = b * SS + s;
        int rows[4] = { dflat, dflat, dflat, dflat };
        process4(rows, 1);
    }

    out_x[(size_t)c * HOUT + lane]      = m0;
    out_x[(size_t)c * HOUT + lane + 32] = m1;
    out_x[(size_t)c * HOUT + lane + 64] = m2;
    out_x[(size_t)c * HOUT + lane + 96] = m3;
}

// ===========================================================================
// launch
// ===========================================================================
extern "C" void kernel_launch(void* const* d_in, const int* in_sizes, int n_in,
                              void* d_out, int out_size)
{
    const float* x   = (const float*)d_in[0];
    const float* pos = (const float*)d_in[1];
    const float* W1 = (const float*)d_in[3];
    const float* B1 = (const float*)d_in[4];
    const float* W2 = (const float*)d_in[5];
    const float* B2 = (const float*)d_in[6];
    const float* W3 = (const float*)d_in[7];
    const float* B3 = (const float*)d_in[8];

    float* out_x = (float*)d_out;
    float* out_c = out_x + (size_t)BB * SS * HOUT;
    float* out_b = out_c + (size_t)BB * SS * 3;

    const size_t fps_smem = (size_t)3 * NN * sizeof(float);   // 192 KB dynamic
    const size_t mlp_smem = (size_t)13760 * sizeof(float);
    cudaFuncSetAttribute(fps_kernel, cudaFuncAttributeMaxDynamicSharedMemorySize, (int)fps_smem);
    cudaFuncSetAttribute(mlp_kernel, cudaFuncAttributeMaxDynamicSharedMemorySize, (int)mlp_smem);

    init_hist_kernel<<<(BB * NCELL + 255) / 256, 256>>>();
    cell_count_kernel<<<(BB * NN + 255) / 256, 256>>>(pos);
    cell_scan_kernel<<<BB, NCELL>>>();
    cell_scatter_kernel<<<(BB * NN + 255) / 256, 256>>>(pos);
    fps_kernel<<<BB, 512, fps_smem>>>(pos, out_c);
    ballq_kernel<<<(BB * SS * 32) / 256, 256>>>(pos, out_b);
    mlp_kernel<<<(BB * SS) / 8, 256, mlp_smem>>>(x, pos, W1, B1, W2, B2, W3, B3, out_x);
}